// round 8
// baseline (speedup 1.0000x reference)
#include <cuda_runtime.h>
#include <math.h>

#define N_NODES 25000
#define N_EDGES 400000
#define HIDDEN  128
#define NUM_RBF 50
#define CUTOFF_R 10.0f

// Output layout (floats): h_updated, v_updated, f_updated, angular_info, dihedral_info, direction_units
#define O_H   0
#define O_V   3200000
#define O_F   12800000
#define O_ANG 64000000
#define O_DIH 67200000
#define O_DU  118400000

// ---------------- scratch ----------------
__device__ float g_unit[3][N_EDGES];
__device__ float g_cw[N_EDGES];
__device__ float g_hAV[N_NODES * 256];   // h @ (W_msgA @ W_vec)  (gathered at col)
__device__ float g_hBV[N_NODES * 256];   // h @ (W_msgB @ W_vec)  (gathered at row)
__device__ float g_WAV[128 * 256];
__device__ float g_WBV[128 * 256];
__device__ float g_WRV[NUM_RBF * 256];
__device__ float g_bV[256];              // b_msg @ W_vec + b_vec
__device__ float g_csA[HIDDEN];
__device__ float g_csD[HIDDEN];

typedef unsigned long long u64;

__device__ __forceinline__ u64 pack2s(float x) {   // (x, x)
    u64 r; unsigned int xi = __float_as_uint(x);
    asm("mov.b64 %0, {%1, %1};" : "=l"(r) : "r"(xi)); return r;
}
__device__ __forceinline__ u64 fma2(u64 a, u64 b, u64 c) {
    u64 d; asm("fma.rn.f32x2 %0, %1, %2, %3;" : "=l"(d) : "l"(a), "l"(b), "l"(c)); return d;
}
__device__ __forceinline__ float2 unpack2(u64 a) {
    unsigned int l, h;
    asm("mov.b64 {%0, %1}, %2;" : "=r"(l), "=r"(h) : "l"(a));
    return make_float2(__uint_as_float(l), __uint_as_float(h));
}
__device__ __forceinline__ float sigmoidf_(float x) { return 1.0f / (1.0f + expf(-x)); }

// ---------------- K1: colsums + fused bias ----------------
__global__ void k_prep(const float* __restrict__ W_ang, const float* __restrict__ W_dih,
                       const float* __restrict__ b_msg, const float* __restrict__ W_vec,
                       const float* __restrict__ b_vec) {
    int k = threadIdx.x;  // 256 threads
    if (k < HIDDEN) {
        float a = 0.f, d = 0.f;
        #pragma unroll 8
        for (int j = 0; j < HIDDEN; j++) {
            a += W_ang[j * HIDDEN + k];
            d += W_dih[j * HIDDEN + k];
        }
        g_csA[k] = a; g_csD[k] = d;
    }
    float b = 0.f;
    #pragma unroll 8
    for (int j = 0; j < HIDDEN; j++) b += b_msg[j] * W_vec[j * 256 + k];
    g_bV[k] = b + b_vec[k];
}

// ---------------- K1b: combined weight products W_msg(306x128) @ W_vec(128x256) ----------------
__global__ void k_prepW(const float* __restrict__ W_msg, const float* __restrict__ W_vec) {
    int r = blockIdx.x;   // 306 rows
    int k = threadIdx.x;  // 128 threads, each does cols k and k+128
    __shared__ float wr[HIDDEN];
    wr[k] = W_msg[r * HIDDEN + k];
    __syncthreads();
    float a = 0.f, b = 0.f;
    #pragma unroll 4
    for (int t = 0; t < HIDDEN; t++) {
        float w = wr[t];
        a += w * W_vec[t * 256 + k];
        b += w * W_vec[t * 256 + 128 + k];
    }
    float* dst = (r < 128) ? &g_WAV[r * 256]
               : (r < 256) ? &g_WBV[(r - 128) * 256]
                           : &g_WRV[(r - 256) * 256];
    dst[k] = a; dst[128 + k] = b;
}

// ---------------- K2: zero direction_units ----------------
__global__ void k_zero_du(float* __restrict__ du) {
    int i = blockIdx.x * blockDim.x + threadIdx.x;
    if (i < N_NODES * 3) du[i] = 0.0f;
}

// ---------------- K3: edge geometry + direction_units scatter ----------------
__global__ void k_geom(const float* __restrict__ pos, const int* __restrict__ ei,
                       float* __restrict__ du) {
    int e = blockIdx.x * blockDim.x + threadIdx.x;
    if (e >= N_EDGES) return;
    int r = ei[e];
    int c = ei[N_EDGES + e];
    float dx = pos[c * 3 + 0] - pos[r * 3 + 0];
    float dy = pos[c * 3 + 1] - pos[r * 3 + 1];
    float dz = pos[c * 3 + 2] - pos[r * 3 + 2];
    float dist = sqrtf(dx * dx + dy * dy + dz * dz) + 1e-8f;
    float inv = 1.0f / dist;
    float ux = dx * inv, uy = dy * inv, uz = dz * inv;
    g_unit[0][e] = ux; g_unit[1][e] = uy; g_unit[2][e] = uz;
    float cw = (dist < CUTOFF_R)
             ? 0.5f * (cosf(3.14159265358979323846f * dist / CUTOFF_R) + 1.0f)
             : 0.0f;
    g_cw[e] = cw;
    atomicAdd(&du[r * 3 + 0],  ux);
    atomicAdd(&du[r * 3 + 1],  uy);
    atomicAdd(&du[r * 3 + 2],  uz);
    atomicAdd(&du[c * 3 + 0], -ux);
    atomicAdd(&du[c * 3 + 1], -uy);
    atomicAdd(&du[c * 3 + 2], -uz);
}

// ---------------- K4: per-node — hAV, hBV, h_updated, angular_info ----------------
// 8 nodes per block, 128 threads. Activations j-major; packed f32x2 over node pairs.
__global__ void __launch_bounds__(128) k_node(
        const float* __restrict__ h,
        const float* __restrict__ W_scalar,
        const float* __restrict__ b_scalar,
        const float* __restrict__ b_ang,
        const float* __restrict__ du,
        float* __restrict__ out) {
    int n0 = blockIdx.x * 8;           // N_NODES % 8 == 0
    int k = threadIdx.x;
    __shared__ __align__(16) float hs[HIDDEN][8];   // [j][node]
    __shared__ float angs[8];
    #pragma unroll
    for (int i = 0; i < 8; i++) hs[k][i] = h[(size_t)(n0 + i) * HIDDEN + k];
    if (k < 8) {
        int n = n0 + k;
        float x = du[n * 3 + 0], y = du[n * 3 + 1], z = du[n * 3 + 2];
        angs[k] = x * x + y * y + z * z;
    }
    __syncthreads();

    u64 aA1[4], aA2[4], aB1[4], aB2[4], aS[4];
    #pragma unroll
    for (int p = 0; p < 4; p++) { aA1[p]=0; aA2[p]=0; aB1[p]=0; aB2[p]=0; aS[p]=0; }

    #pragma unroll 2
    for (int j = 0; j < HIDDEN; j++) {
        u64 wA1 = pack2s(g_WAV[j * 256 + k]);
        u64 wA2 = pack2s(g_WAV[j * 256 + 128 + k]);
        u64 wB1 = pack2s(g_WBV[j * 256 + k]);
        u64 wB2 = pack2s(g_WBV[j * 256 + 128 + k]);
        u64 wS  = pack2s(W_scalar[j * HIDDEN + k]);
        ulonglong2 sa = *reinterpret_cast<const ulonglong2*>(&hs[j][0]);
        ulonglong2 sb = *reinterpret_cast<const ulonglong2*>(&hs[j][4]);
        u64 s[4] = {sa.x, sa.y, sb.x, sb.y};
        #pragma unroll
        for (int p = 0; p < 4; p++) {
            aA1[p] = fma2(s[p], wA1, aA1[p]);
            aA2[p] = fma2(s[p], wA2, aA2[p]);
            aB1[p] = fma2(s[p], wB1, aB1[p]);
            aB2[p] = fma2(s[p], wB2, aB2[p]);
            aS[p]  = fma2(s[p], wS,  aS[p]);
        }
    }

    float csA = g_csA[k], ba = b_ang[k], bs = b_scalar[k];
    #pragma unroll
    for (int p = 0; p < 4; p++) {
        float2 vA1 = unpack2(aA1[p]), vA2 = unpack2(aA2[p]);
        float2 vB1 = unpack2(aB1[p]), vB2 = unpack2(aB2[p]);
        float2 vS  = unpack2(aS[p]);
        float A1[2] = {vA1.x, vA1.y}, A2[2] = {vA2.x, vA2.y};
        float B1[2] = {vB1.x, vB1.y}, B2[2] = {vB2.x, vB2.y};
        float S [2] = {vS.x,  vS.y};
        #pragma unroll
        for (int l = 0; l < 2; l++) {
            int i = 2 * p + l;
            int n = n0 + i;
            g_hAV[(size_t)n * 256 + k]       = A1[l];
            g_hAV[(size_t)n * 256 + 128 + k] = A2[l];
            g_hBV[(size_t)n * 256 + k]       = B1[l];
            g_hBV[(size_t)n * 256 + 128 + k] = B2[l];
            float ang  = angs[i];
            float gate = sigmoidf_(ang * csA + ba);
            out[O_H   + (size_t)n * HIDDEN + k] = hs[k][i] + (S[l] + bs) * gate;
            out[O_ANG + (size_t)n * HIDDEN + k] = ang;
        }
    }
}

// ---------------- K5: fused vec path — rbf mini-GEMM + gathers + vec_msg scatter ----------------
// 16 edges per block, 128 threads.
__global__ void __launch_bounds__(128) k_edge(
        const float* __restrict__ v, const int* __restrict__ ei,
        const float* __restrict__ rbf, float* __restrict__ out_v) {
    const int EB = 16;
    int e0 = blockIdx.x * EB;          // N_EDGES % 16 == 0
    int k = threadIdx.x;
    __shared__ __align__(16) float rs[NUM_RBF][EB];     // [rbf][edge]
    __shared__ __align__(16) float m[EB][3 * HIDDEN];   // messages
    __shared__ float s_u[3][EB], s_cw[EB];
    __shared__ int s_row[EB], s_col[EB];

    for (int t = k; t < EB * NUM_RBF; t += 128) {
        int i = t / NUM_RBF, r = t - i * NUM_RBF;
        rs[r][i] = rbf[(size_t)(e0 + i) * NUM_RBF + r];
    }
    if (k < EB) {
        int e = e0 + k;
        s_row[k] = ei[e]; s_col[k] = ei[N_EDGES + e];
        s_u[0][k] = g_unit[0][e]; s_u[1][k] = g_unit[1][e]; s_u[2][k] = g_unit[2][e];
        s_cw[k] = g_cw[e];
    }
    __syncthreads();

    u64 a1[8], a2[8];
    #pragma unroll
    for (int p = 0; p < 8; p++) { a1[p] = 0; a2[p] = 0; }

    #pragma unroll 2
    for (int r = 0; r < NUM_RBF; r++) {
        u64 w1 = pack2s(g_WRV[r * 256 + k]);
        u64 w2 = pack2s(g_WRV[r * 256 + 128 + k]);
        #pragma unroll
        for (int q = 0; q < 4; q++) {
            ulonglong2 s2 = *reinterpret_cast<const ulonglong2*>(&rs[r][4 * q]);
            a1[2 * q]     = fma2(s2.x, w1, a1[2 * q]);
            a2[2 * q]     = fma2(s2.x, w2, a2[2 * q]);
            a1[2 * q + 1] = fma2(s2.y, w1, a1[2 * q + 1]);
            a2[2 * q + 1] = fma2(s2.y, w2, a2[2 * q + 1]);
        }
    }

    float v1[EB], v2[EB];
    #pragma unroll
    for (int p = 0; p < 8; p++) {
        float2 f1 = unpack2(a1[p]), f2 = unpack2(a2[p]);
        v1[2 * p] = f1.x; v1[2 * p + 1] = f1.y;
        v2[2 * p] = f2.x; v2[2 * p + 1] = f2.y;
    }

    float bV1 = g_bV[k], bV2 = g_bV[128 + k];

    #pragma unroll 4
    for (int i = 0; i < EB; i++) {
        int r_ = s_row[i], c_ = s_col[i];
        float cw = s_cw[i];
        float w1 = (v1[i] + g_hAV[(size_t)c_ * 256 + k]
                          + g_hBV[(size_t)r_ * 256 + k] + bV1) * cw;
        float w2 = (v2[i] + g_hAV[(size_t)c_ * 256 + 128 + k]
                          + g_hBV[(size_t)r_ * 256 + 128 + k] + bV2) * cw;
        const float* vr = v + (size_t)r_ * 3 * HIDDEN;
        m[i][k]              = w1 * s_u[0][i] + w2 * vr[k];
        m[i][HIDDEN + k]     = w1 * s_u[1][i] + w2 * vr[HIDDEN + k];
        m[i][2 * HIDDEN + k] = w1 * s_u[2][i] + w2 * vr[2 * HIDDEN + k];
    }
    __syncthreads();

    for (int t = k; t < EB * 96; t += 128) {
        int i = t / 96, q = t - i * 96;
        float4 val = *reinterpret_cast<float4*>(&m[i][q * 4]);
        int c_ = s_col[i];
        atomicAdd(reinterpret_cast<float4*>(out_v + (size_t)c_ * 3 * HIDDEN + q * 4), val);
    }
}

// ---------------- K6: dihedral + f gating — 32 edges/block, packed f32x2 ----------------
__global__ void __launch_bounds__(128) k_fgate(
        const float* __restrict__ f, const int* __restrict__ ei,
        const float* __restrict__ W_edge, const float* __restrict__ b_edge,
        const float* __restrict__ b_dih, const float* __restrict__ du,
        float* __restrict__ out) {
    int e0 = blockIdx.x * 32;          // N_EDGES % 32 == 0
    int k = threadIdx.x;
    __shared__ __align__(16) float fs[HIDDEN][32];   // [j][edge]
    __shared__ float dihs[32];
    #pragma unroll
    for (int i = 0; i < 32; i++) fs[k][i] = f[(size_t)(e0 + i) * HIDDEN + k];
    if (k < 32) {
        int e = e0 + k;
        int r = ei[e], c = ei[N_EDGES + e];
        float ux = g_unit[0][e], uy = g_unit[1][e], uz = g_unit[2][e];
        float vix = du[r * 3 + 0], viy = du[r * 3 + 1], viz = du[r * 3 + 2];
        float vjx = du[c * 3 + 0], vjy = du[c * 3 + 1], vjz = du[c * 3 + 2];
        float di = vix * ux + viy * uy + viz * uz;
        float dj = vjx * ux + vjy * uy + vjz * uz;
        float ax = vix - di * ux, ay = viy - di * uy, az = viz - di * uz;
        float bx = vjx - dj * ux, by = vjy - dj * uy, bz = vjz - dj * uz;
        dihs[k] = ax * bx + ay * by + az * bz;
    }
    __syncthreads();

    u64 acc[16];
    #pragma unroll
    for (int p = 0; p < 16; p++) acc[p] = 0;

    #pragma unroll 2
    for (int j = 0; j < HIDDEN; j++) {
        u64 w = pack2s(W_edge[j * HIDDEN + k]);
        #pragma unroll
        for (int q = 0; q < 8; q++) {
            ulonglong2 s2 = *reinterpret_cast<const ulonglong2*>(&fs[j][4 * q]);
            acc[2 * q]     = fma2(s2.x, w, acc[2 * q]);
            acc[2 * q + 1] = fma2(s2.y, w, acc[2 * q + 1]);
        }
    }

    float csD = g_csD[k], bd = b_dih[k], be = b_edge[k];
    #pragma unroll
    for (int p = 0; p < 16; p++) {
        float2 va = unpack2(acc[p]);
        float a[2] = {va.x, va.y};
        #pragma unroll
        for (int l = 0; l < 2; l++) {
            int i = 2 * p + l;
            size_t e = (size_t)e0 + i;
            float dih  = dihs[i];
            float gate = sigmoidf_(dih * csD + bd);
            out[O_F   + e * HIDDEN + k] = fs[k][i] + (a[l] + be) * gate;
            out[O_DIH + e * HIDDEN + k] = dih;
        }
    }
}

// ---------------- launch ----------------
extern "C" void kernel_launch(void* const* d_in, const int* in_sizes, int n_in,
                              void* d_out, int out_size) {
    const float* h        = (const float*)d_in[0];
    const float* v        = (const float*)d_in[1];
    const float* f        = (const float*)d_in[2];
    const float* pos      = (const float*)d_in[3];
    const float* edge_rbf = (const float*)d_in[4];
    const int*   ei       = (const int*)  d_in[5];
    const float* W_msg    = (const float*)d_in[6];
    const float* b_msg    = (const float*)d_in[7];
    const float* W_vec    = (const float*)d_in[8];
    const float* b_vec    = (const float*)d_in[9];
    const float* W_scalar = (const float*)d_in[10];
    const float* b_scalar = (const float*)d_in[11];
    const float* W_edge   = (const float*)d_in[12];
    const float* b_edge   = (const float*)d_in[13];
    const float* W_ang    = (const float*)d_in[14];
    const float* b_ang    = (const float*)d_in[15];
    const float* W_dih    = (const float*)d_in[16];
    const float* b_dih    = (const float*)d_in[17];
    float* out = (float*)d_out;

    cudaMemcpyAsync(out + O_V, v, (size_t)N_NODES * 3 * HIDDEN * sizeof(float),
                    cudaMemcpyDeviceToDevice, 0);

    k_prep<<<1, 256>>>(W_ang, W_dih, b_msg, W_vec, b_vec);
    k_prepW<<<306, 128>>>(W_msg, W_vec);
    k_zero_du<<<(N_NODES * 3 + 255) / 256, 256>>>(out + O_DU);
    k_geom<<<(N_EDGES + 255) / 256, 256>>>(pos, ei, out + O_DU);
    k_node<<<N_NODES / 8, 128>>>(h, W_scalar, b_scalar, b_ang, out + O_DU, out);
    k_edge<<<N_EDGES / 16, 128>>>(v, ei, edge_rbf, out + O_V);
    k_fgate<<<N_EDGES / 32, 128>>>(f, ei, W_edge, b_edge, b_dih, out + O_DU, out);
}